// round 16
// baseline (speedup 1.0000x reference)
#include <cuda_runtime.h>
#include <cuda_bf16.h>
#include <cstdint>
#include <cstddef>

#define D_MODEL 1024
#define NH      16
#define DK      64
#define BATCH   2
#define SEQ     2048
#define M_ROWS  (BATCH * SEQ)                 // 4096
#define OUT_ELEMS ((size_t)M_ROWS * D_MODEL)  // 4194304

// ---------------------------------------------------------------------------
// Scratch (allocation-free rule: __device__ globals)
// ---------------------------------------------------------------------------
__device__ float g_ctx[M_ROWS * D_MODEL];          // [b,s,D]
__device__ __nv_bfloat16 g_bh[D_MODEL * D_MODEL];  // weight^T hi  [n][k]
__device__ __nv_bfloat16 g_bl[D_MODEL * D_MODEL];  // weight^T lo  [n][k]
// attention operands, bf16 hi/lo
__device__ __nv_bfloat16 g_qh[BATCH * NH * SEQ * DK];  // [b,h,s,d]
__device__ __nv_bfloat16 g_ql[BATCH * NH * SEQ * DK];
__device__ __nv_bfloat16 g_kh[BATCH * NH * SEQ * DK];  // [b,h,s,d]
__device__ __nv_bfloat16 g_kl[BATCH * NH * SEQ * DK];
__device__ __nv_bfloat16 g_vh[BATCH * NH * SEQ * DK];  // [b,h,d,s]
__device__ __nv_bfloat16 g_vl[BATCH * NH * SEQ * DK];

// ===========================================================================
// small helpers
// ===========================================================================
__device__ __forceinline__ void mma16816(float* c, const uint32_t* a,
                                         const uint32_t* b)
{
    asm volatile(
        "mma.sync.aligned.m16n8k16.row.col.f32.bf16.bf16.f32 "
        "{%0,%1,%2,%3}, {%4,%5,%6,%7}, {%8,%9}, {%0,%1,%2,%3};"
        : "+f"(c[0]), "+f"(c[1]), "+f"(c[2]), "+f"(c[3])
        : "r"(a[0]), "r"(a[1]), "r"(a[2]), "r"(a[3]), "r"(b[0]), "r"(b[1]));
}

// split two fp32 into packed-bf16x2 hi word and lo word
__device__ __forceinline__ void split2(float a, float b,
                                       uint32_t& hi, uint32_t& lo) {
    __nv_bfloat16 ha = __float2bfloat16(a), hb = __float2bfloat16(b);
    __nv_bfloat16 la = __float2bfloat16(a - __bfloat162float(ha));
    __nv_bfloat16 lb = __float2bfloat16(b - __bfloat162float(hb));
    hi = ((uint32_t)__bfloat16_as_ushort(hb) << 16) | __bfloat16_as_ushort(ha);
    lo = ((uint32_t)__bfloat16_as_ushort(lb) << 16) | __bfloat16_as_ushort(la);
}

// ===========================================================================
// weight fp32 [k][n] -> bf16 hi/lo transposed [n][k]  (32x32 smem tiles)
// ===========================================================================
__global__ __launch_bounds__(256) void conv_wt(
    const float* __restrict__ W, __nv_bfloat16* __restrict__ hi,
    __nv_bfloat16* __restrict__ lo)
{
    __shared__ float t[32][33];
    int bx = blockIdx.x, by = blockIdx.y;
    int x = threadIdx.x, y = threadIdx.y;      // 32 x 8
#pragma unroll
    for (int j = 0; j < 4; j++)
        t[y + j * 8][x] = W[(size_t)(by * 32 + y + j * 8) * D_MODEL + bx * 32 + x];
    __syncthreads();
#pragma unroll
    for (int j = 0; j < 4; j++) {
        float v = t[x][y + j * 8];
        __nv_bfloat16 h = __float2bfloat16(v);
        __nv_bfloat16 l = __float2bfloat16(v - __bfloat162float(h));
        size_t o = (size_t)(bx * 32 + y + j * 8) * D_MODEL + by * 32 + x;
        hi[o] = h;
        lo[o] = l;
    }
}

// ===========================================================================
// HMMA bf16x3 GEMM, fp32 A with inline hi/lo split.
// C[4096,1024] = A_fp32[4096,1024] @ Wt[n][k]^T + bias.
// Block 128m x 256n, 512 threads / 16 warps (2m x 8n), warp tile 64x32:
//   48 LDS / 48 MMA per k16 (ratio 1.0), ~115 live regs (no spill at the
//   128-reg cap), 4 warps/SMSP, grid = 128 blocks = 1 wave.
// K-slab 32, double-buffered smem, 3 MMA products: Ah*Bh + Ah*Bl + Al*Bh.
// mode 0: write bf16 hi/lo [b,h,s,d] (Q, K)
// mode 1: write bf16 hi/lo [b,h,d,s] (V)
// mode 2: write fp32 row-major [m,n] (final out)
// ===========================================================================
#define GEMM_AH_OFF 0
#define GEMM_AL_OFF 2560
#define GEMM_BH_OFF 5120
#define GEMM_BL_OFF 10240
#define GEMM_BUF_U32 15360
#define GEMM_SMEM_BYTES (2 * GEMM_BUF_U32 * 4)     // 122880 B

__global__ __launch_bounds__(512, 1) void gemm_hmma(
    const float* __restrict__ A,
    const __nv_bfloat16* __restrict__ Bh, const __nv_bfloat16* __restrict__ Bl,
    const float* __restrict__ bias, float* __restrict__ C,
    __nv_bfloat16* __restrict__ Ch, __nv_bfloat16* __restrict__ Cl, int mode)
{
    extern __shared__ uint32_t sm32[];
    int tid = threadIdx.x;
    int wid = tid >> 5, lane = tid & 31;
    int bm = blockIdx.y * 128;
    int bn = blockIdx.x * 256;
    int wm = (wid & 1) * 64;          // 2 m-halves
    int wn = (wid >> 1) * 32;         // 8 n-groups
    int g = lane >> 2, cc = lane & 3;

    const float* Asrc = A + (size_t)bm * D_MODEL;
    const __nv_bfloat16* Bhsrc = Bh + (size_t)bn * D_MODEL;
    const __nv_bfloat16* Blsrc = Bl + (size_t)bn * D_MODEL;

    float acc[4][4][4];
#pragma unroll
    for (int i = 0; i < 4; i++)
#pragma unroll
        for (int j = 0; j < 4; j++)
#pragma unroll
            for (int u = 0; u < 4; u++) acc[i][j][u] = 0.f;

    auto load_slab = [&](int buf, int k0) {
        uint32_t* Ah_t = sm32 + buf * GEMM_BUF_U32 + GEMM_AH_OFF;
        uint32_t* Al_t = sm32 + buf * GEMM_BUF_U32 + GEMM_AL_OFF;
        uint32_t* Bh_t = sm32 + buf * GEMM_BUF_U32 + GEMM_BH_OFF;
        uint32_t* Bl_t = sm32 + buf * GEMM_BUF_U32 + GEMM_BL_OFF;
        // A: fp32 128 rows x 8 float4 segs, split inline -> hi/lo tiles
#pragma unroll
        for (int i = 0; i < 2; i++) {
            int flat = tid + i * 512;            // 0..1023
            int row = flat >> 3, seg = flat & 7;
            float4 v = *(const float4*)(Asrc + (size_t)row * D_MODEL + k0 + seg * 4);
            uint32_t h0, l0, h1, l1;
            split2(v.x, v.y, h0, l0);
            split2(v.z, v.w, h1, l1);
            *(uint2*)(Ah_t + row * 20 + seg * 2) = make_uint2(h0, h1);
            *(uint2*)(Al_t + row * 20 + seg * 2) = make_uint2(l0, l1);
        }
        // B: 256 rows x 4 uint4 segs per tile (bf16 hi and lo)
#pragma unroll
        for (int i = 0; i < 2; i++) {
            int flat = tid + i * 512;            // 0..1023
            int row = flat >> 2, seg = flat & 3;
            uint4 v = *(const uint4*)(Bhsrc + (size_t)row * D_MODEL + k0 + seg * 8);
            *(uint4*)(Bh_t + row * 20 + seg * 4) = v;
            uint4 w = *(const uint4*)(Blsrc + (size_t)row * D_MODEL + k0 + seg * 8);
            *(uint4*)(Bl_t + row * 20 + seg * 4) = w;
        }
    };

    load_slab(0, 0);
    __syncthreads();

    for (int s = 0; s < 32; s++) {
        int buf = s & 1;
        if (s + 1 < 32) load_slab(buf ^ 1, (s + 1) * 32);

        const uint32_t* As_h = sm32 + buf * GEMM_BUF_U32 + GEMM_AH_OFF;
        const uint32_t* As_l = sm32 + buf * GEMM_BUF_U32 + GEMM_AL_OFF;
        const uint32_t* Bs_h = sm32 + buf * GEMM_BUF_U32 + GEMM_BH_OFF;
        const uint32_t* Bs_l = sm32 + buf * GEMM_BUF_U32 + GEMM_BL_OFF;

#pragma unroll
        for (int ks = 0; ks < 2; ks++) {
            uint32_t bhf[4][2], blf[4][2];
#pragma unroll
            for (int j = 0; j < 4; j++) {
                int idx = (wn + j * 8 + g) * 20 + cc + ks * 8;
                bhf[j][0] = Bs_h[idx]; bhf[j][1] = Bs_h[idx + 4];
                blf[j][0] = Bs_l[idx]; blf[j][1] = Bs_l[idx + 4];
            }
#pragma unroll
            for (int i = 0; i < 4; i++) {
                int idx0 = (wm + i * 16 + g) * 20 + cc + ks * 8;
                int idx1 = idx0 + 8 * 20;
                uint32_t ahf[4] = { As_h[idx0], As_h[idx1],
                                    As_h[idx0 + 4], As_h[idx1 + 4] };
                uint32_t alf[4] = { As_l[idx0], As_l[idx1],
                                    As_l[idx0 + 4], As_l[idx1 + 4] };
#pragma unroll
                for (int j = 0; j < 4; j++) {
                    mma16816(acc[i][j], ahf, bhf[j]);
                    mma16816(acc[i][j], ahf, blf[j]);
                    mma16816(acc[i][j], alf, bhf[j]);
                }
            }
        }
        __syncthreads();
    }

#pragma unroll
    for (int i = 0; i < 4; i++) {
        int m0 = bm + wm + i * 16 + g;
#pragma unroll
        for (int j = 0; j < 4; j++) {
            int n = bn + wn + j * 8 + cc * 2;
            float b0 = bias[n], b1 = bias[n + 1];
            float v00 = acc[i][j][0] + b0, v01 = acc[i][j][1] + b1;
            float v10 = acc[i][j][2] + b0, v11 = acc[i][j][3] + b1;
            int b_ = m0 >> 11, s0 = m0 & 2047, s1 = (m0 + 8) & 2047;
            int h = n >> 6, d = n & 63;
            if (mode == 2) {
                *(float2*)&C[(size_t)m0 * D_MODEL + n]       = make_float2(v00, v01);
                *(float2*)&C[(size_t)(m0 + 8) * D_MODEL + n] = make_float2(v10, v11);
            } else if (mode == 0) {
                size_t base0 = (((size_t)(b_ * NH + h)) * SEQ + s0) * DK + d;
                size_t base1 = (((size_t)(b_ * NH + h)) * SEQ + s1) * DK + d;
                uint32_t hi0, lo0, hi1, lo1;
                split2(v00, v01, hi0, lo0);
                split2(v10, v11, hi1, lo1);
                *(uint32_t*)&Ch[base0] = hi0;  *(uint32_t*)&Cl[base0] = lo0;
                *(uint32_t*)&Ch[base1] = hi1;  *(uint32_t*)&Cl[base1] = lo1;
            } else {  // mode 1: [b,h,d,s]
                __nv_bfloat16* bch = Ch + ((size_t)(b_ * NH + h)) * DK * SEQ;
                __nv_bfloat16* bcl = Cl + ((size_t)(b_ * NH + h)) * DK * SEQ;
                float vv[4] = { v00, v01, v10, v11 };
                int ds[4]   = { d, d + 1, d, d + 1 };
                int ss[4]   = { s0, s0, s1, s1 };
#pragma unroll
                for (int u = 0; u < 4; u++) {
                    __nv_bfloat16 hh = __float2bfloat16(vv[u]);
                    __nv_bfloat16 ll = __float2bfloat16(vv[u] - __bfloat162float(hh));
                    size_t o = (size_t)ds[u] * SEQ + ss[u];
                    bch[o] = hh;
                    bcl[o] = ll;
                }
            }
        }
    }
}

// ===========================================================================
// Streaming flash-style attention (unchanged — R12/R13/R14-proven).
// 64 q-rows/block, 512 threads; scores->exp->(gmem e)+(PV) per 256-wide tile;
// shift-free softmax; attn rescaled in-block at the end.
// ===========================================================================
#define QT 64
#define EB_STRIDE 264
#define EB_SZ     (QT * EB_STRIDE)          // 16896 u32
#define KH_OFF    EB_SZ
#define KL_OFF    (KH_OFF + 8192)
#define VH_OFF    (KL_OFF + 8192)
#define VL_OFF    (VH_OFF + 8192)
#define FLASH_SMEM_U32  (VL_OFF + 8192)     // 49664 u32
#define FLASH_SMEM_BYTES (FLASH_SMEM_U32 * 4)  // 198656 B

__global__ __launch_bounds__(512, 1) void attn_flash(
    const __nv_bfloat16* __restrict__ qh, const __nv_bfloat16* __restrict__ ql,
    const __nv_bfloat16* __restrict__ kh, const __nv_bfloat16* __restrict__ kl,
    const __nv_bfloat16* __restrict__ vh, const __nv_bfloat16* __restrict__ vl,
    float* __restrict__ attn_out, float* __restrict__ ctx)
{
    extern __shared__ uint32_t sm[];
    float*    EBf = (float*)sm;
    uint32_t* KH  = sm + KH_OFF;
    uint32_t* KL  = sm + KL_OFF;
    uint32_t* VH  = sm + VH_OFF;
    uint32_t* VL  = sm + VL_OFF;

    int tid = threadIdx.x;
    int wid = tid >> 5, lane = tid & 31;
    int g = lane >> 2, cc = lane & 3;
    int qw = wid & 3, kw = wid >> 2;
    int bh = blockIdx.y;
    int b = bh >> 4, h = bh & 15;
    int q0 = blockIdx.x * QT;
    int r0 = qw * 16 + g, r1 = r0 + 8;

    const __nv_bfloat16* Qh = qh + (size_t)bh * SEQ * DK;
    const __nv_bfloat16* Ql = ql + (size_t)bh * SEQ * DK;
    const uint32_t* Kh32 = (const uint32_t*)(kh + (size_t)bh * SEQ * DK);
    const uint32_t* Kl32 = (const uint32_t*)(kl + (size_t)bh * SEQ * DK);
    const uint32_t* Vh32 = (const uint32_t*)(vh + (size_t)bh * DK * SEQ);
    const uint32_t* Vl32 = (const uint32_t*)(vl + (size_t)bh * DK * SEQ);

    uint32_t qfh[4][4], qfl[4][4];
    {
        const __nv_bfloat16* r0h = Qh + (size_t)(q0 + r0) * DK;
        const __nv_bfloat16* r1h = Qh + (size_t)(q0 + r1) * DK;
        const __nv_bfloat16* r0l = Ql + (size_t)(q0 + r0) * DK;
        const __nv_bfloat16* r1l = Ql + (size_t)(q0 + r1) * DK;
#pragma unroll
        for (int kst = 0; kst < 4; kst++) {
            int c0 = kst * 16 + cc * 2;
            qfh[kst][0] = *(const uint32_t*)(r0h + c0);
            qfh[kst][1] = *(const uint32_t*)(r1h + c0);
            qfh[kst][2] = *(const uint32_t*)(r0h + c0 + 8);
            qfh[kst][3] = *(const uint32_t*)(r1h + c0 + 8);
            qfl[kst][0] = *(const uint32_t*)(r0l + c0);
            qfl[kst][1] = *(const uint32_t*)(r1l + c0);
            qfl[kst][2] = *(const uint32_t*)(r0l + c0 + 8);
            qfl[kst][3] = *(const uint32_t*)(r1l + c0 + 8);
        }
    }

    float srow0 = 0.f, srow1 = 0.f;
    float cacc[2][4];
#pragma unroll
    for (int j = 0; j < 2; j++)
#pragma unroll
        for (int u = 0; u < 4; u++) cacc[j][u] = 0.f;

    for (int kt = 0; kt < 8; kt++) {
        __syncthreads();
#pragma unroll
        for (int i = 0; i < 4; i++) {
            int flat = tid + i * 512;
            {
                int row = flat >> 3, c4 = flat & 7;
                int dst = row * 32 + ((c4 * 4) ^ ((row & 7) << 2));
                *(uint4*)&KH[dst] = *(const uint4*)&Kh32[(size_t)(kt * 256 + row) * 32 + c4 * 4];
                *(uint4*)&KL[dst] = *(const uint4*)&Kl32[(size_t)(kt * 256 + row) * 32 + c4 * 4];
            }
            {
                int row = flat >> 5, c4 = flat & 31;
                int dst = row * 128 + ((c4 * 4) ^ ((row & 7) << 2));
                *(uint4*)&VH[dst] = *(const uint4*)&Vh32[(size_t)row * 1024 + kt * 128 + c4 * 4];
                *(uint4*)&VL[dst] = *(const uint4*)&Vl32[(size_t)row * 1024 + kt * 128 + c4 * 4];
            }
        }
        __syncthreads();

#pragma unroll
        for (int j = 0; j < 8; j++) {
            float sacc[4] = {0.f, 0.f, 0.f, 0.f};
#pragma unroll
            for (int kst = 0; kst < 4; kst++) {
                int base = (kw * 64 + j * 8 + g) * 32;
                int c0 = (cc + kst * 8) ^ (g << 2);
                int c1 = (cc + 4 + kst * 8) ^ (g << 2);
                uint32_t bhf[2] = { KH[base + c0], KH[base + c1] };
                uint32_t blf[2] = { KL[base + c0], KL[base + c1] };
                mma16816(sacc, qfh[kst], bhf);
                mma16816(sacc, qfh[kst], blf);
                mma16816(sacc, qfl[kst], bhf);
            }
            float e0 = __expf(sacc[0] * 0.125f);
            float e1 = __expf(sacc[1] * 0.125f);
            float e2 = __expf(sacc[2] * 0.125f);
            float e3 = __expf(sacc[3] * 0.125f);
            srow0 += e0 + e1;
            srow1 += e2 + e3;
            int col = kw * 64 + j * 8 + cc * 2;
            *(float2*)&EBf[r0 * EB_STRIDE + col] = make_float2(e0, e1);
            *(float2*)&EBf[r1 * EB_STRIDE + col] = make_float2(e2, e3);
        }
        __syncthreads();

#pragma unroll
        for (int i = 0; i < 8; i++) {
            int flat = tid + i * 512;
            int row = flat >> 6, c = (flat & 63) * 4;
            float4 v = *(const float4*)&EBf[row * EB_STRIDE + c];
            *(float4*)&attn_out[((size_t)bh * SEQ + q0 + row) * SEQ + kt * 256 + c] = v;
        }

#pragma unroll 2
        for (int kst = 0; kst < 16; kst++) {
            int k0 = kst * 16;
            uint32_t ahf[4], alf[4];
            float2 p;
            p = *(const float2*)&EBf[r0 * EB_STRIDE + k0 + cc * 2];
            split2(p.x, p.y, ahf[0], alf[0]);
            p = *(const float2*)&EBf[r1 * EB_STRIDE + k0 + cc * 2];
            split2(p.x, p.y, ahf[1], alf[1]);
            p = *(const float2*)&EBf[r0 * EB_STRIDE + k0 + 8 + cc * 2];
            split2(p.x, p.y, ahf[2], alf[2]);
            p = *(const float2*)&EBf[r1 * EB_STRIDE + k0 + 8 + cc * 2];
            split2(p.x, p.y, ahf[3], alf[3]);
#pragma unroll
            for (int j = 0; j < 2; j++) {
                int base = (kw * 16 + j * 8 + g) * 128;
                int c0 = (cc + kst * 8) ^ (g << 2);
                int c1 = (cc + 4 + kst * 8) ^ (g << 2);
                uint32_t bhf[2] = { VH[base + c0], VH[base + c1] };
                uint32_t blf[2] = { VL[base + c0], VL[base + c1] };
                mma16816(cacc[j], ahf, bhf);
                mma16816(cacc[j], ahf, blf);
                mma16816(cacc[j], alf, bhf);
            }
        }
    }
    __syncthreads();

    srow0 += __shfl_xor_sync(0xffffffffu, srow0, 1);
    srow0 += __shfl_xor_sync(0xffffffffu, srow0, 2);
    srow1 += __shfl_xor_sync(0xffffffffu, srow1, 1);
    srow1 += __shfl_xor_sync(0xffffffffu, srow1, 2);
    if (cc == 0) {
        EBf[r0 * 4 + kw] = srow0;
        EBf[r1 * 4 + kw] = srow1;
    }
    __syncthreads();
    if (tid < 64) {
        float s = EBf[tid * 4] + EBf[tid * 4 + 1] + EBf[tid * 4 + 2] + EBf[tid * 4 + 3];
        EBf[256 + tid] = 1.0f / s;
    }
    __syncthreads();

    {
        float inv0 = EBf[256 + r0], inv1 = EBf[256 + r1];
#pragma unroll
        for (int j = 0; j < 2; j++) {
            int col = h * DK + kw * 16 + j * 8 + cc * 2;
            *(float2*)&ctx[((size_t)(b * SEQ) + q0 + r0) * D_MODEL + col] =
                make_float2(cacc[j][0] * inv0, cacc[j][1] * inv0);
            *(float2*)&ctx[((size_t)(b * SEQ) + q0 + r1) * D_MODEL + col] =
                make_float2(cacc[j][2] * inv1, cacc[j][3] * inv1);
        }
    }

    {
        int row = tid >> 3, t8 = tid & 7;
        float inv = EBf[256 + row];
        float* arow = attn_out + ((size_t)bh * SEQ + q0 + row) * SEQ;
#pragma unroll 4
        for (int i = 0; i < 64; i++) {
            int c = (t8 + i * 8) * 4;
            float4 v = *(float4*)&arow[c];
            v.x *= inv; v.y *= inv; v.z *= inv; v.w *= inv;
            *(float4*)&arow[c] = v;
        }
    }
}

// ---------------------------------------------------------------------------
extern "C" void kernel_launch(void* const* d_in, const int* in_sizes, int n_in,
                              void* d_out, int out_size)
{
    const float* query = (const float*)d_in[0];
    const float* key   = (const float*)d_in[1];
    const float* value = (const float*)d_in[2];
    const float* Wq = (const float*)d_in[3];
    const float* bq = (const float*)d_in[4];
    const float* Wk = (const float*)d_in[5];
    const float* bk = (const float*)d_in[6];
    const float* Wv = (const float*)d_in[7];
    const float* bv = (const float*)d_in[8];
    const float* Wo = (const float*)d_in[9];
    const float* bo = (const float*)d_in[10];

    float* out  = (float*)d_out;
    float* attn = out + OUT_ELEMS;

    float* gctx;
    __nv_bfloat16 *bh_, *bl_, *qh, *ql, *kh, *kl, *vh, *vl;
    cudaGetSymbolAddress((void**)&gctx, g_ctx);
    cudaGetSymbolAddress((void**)&bh_,  g_bh);
    cudaGetSymbolAddress((void**)&bl_,  g_bl);
    cudaGetSymbolAddress((void**)&qh,   g_qh);
    cudaGetSymbolAddress((void**)&ql,   g_ql);
    cudaGetSymbolAddress((void**)&kh,   g_kh);
    cudaGetSymbolAddress((void**)&kl,   g_kl);
    cudaGetSymbolAddress((void**)&vh,   g_vh);
    cudaGetSymbolAddress((void**)&vl,   g_vl);

    cudaFuncSetAttribute(gemm_hmma,
                         cudaFuncAttributeMaxDynamicSharedMemorySize,
                         GEMM_SMEM_BYTES);
    cudaFuncSetAttribute(attn_flash,
                         cudaFuncAttributeMaxDynamicSharedMemorySize,
                         FLASH_SMEM_BYTES);

    dim3 gg(D_MODEL / 256, M_ROWS / 128);     // (4, 32) = 128 blocks = 1 wave
    dim3 wtg(32, 32);
    dim3 wtb(32, 8);

    // Q projection -> bf16 hi/lo [b,h,s,d]   (fp32 A, inline split)
    conv_wt<<<wtg, wtb>>>(Wq, bh_, bl_);
    gemm_hmma<<<gg, 512, GEMM_SMEM_BYTES>>>(query, bh_, bl_, bq, nullptr, qh, ql, 0);
    // K projection -> bf16 hi/lo [b,h,s,d]
    conv_wt<<<wtg, wtb>>>(Wk, bh_, bl_);
    gemm_hmma<<<gg, 512, GEMM_SMEM_BYTES>>>(key, bh_, bl_, bk, nullptr, kh, kl, 0);
    // V projection -> bf16 hi/lo [b,h,d,s]
    conv_wt<<<wtg, wtb>>>(Wv, bh_, bl_);
    gemm_hmma<<<gg, 512, GEMM_SMEM_BYTES>>>(value, bh_, bl_, bv, nullptr, vh, vl, 1);

    // streaming attention (scores+softmax+attn-write+PV fused)
    attn_flash<<<dim3(SEQ / QT, BATCH * NH), 512, FLASH_SMEM_BYTES>>>(
        qh, ql, kh, kl, vh, vl, attn, gctx);

    // output projection (fp32 A = ctx, fp32 out)
    conv_wt<<<wtg, wtb>>>(Wo, bh_, bl_);
    gemm_hmma<<<gg, 512, GEMM_SMEM_BYTES>>>(gctx, bh_, bl_, bo, out, nullptr, nullptr, 2);
}

// round 17
// speedup vs baseline: 1.0041x; 1.0041x over previous
#include <cuda_runtime.h>
#include <cuda_bf16.h>
#include <cstdint>
#include <cstddef>

#define D_MODEL 1024
#define NH      16
#define DK      64
#define BATCH   2
#define SEQ     2048
#define M_ROWS  (BATCH * SEQ)                 // 4096
#define OUT_ELEMS ((size_t)M_ROWS * D_MODEL)  // 4194304

// ---------------------------------------------------------------------------
// Scratch (allocation-free rule: __device__ globals)
// ---------------------------------------------------------------------------
__device__ float g_ctx[M_ROWS * D_MODEL];          // [b,s,D]
__device__ __nv_bfloat16 g_bh[D_MODEL * D_MODEL];  // weight^T hi  [n][k]
__device__ __nv_bfloat16 g_bl[D_MODEL * D_MODEL];  // weight^T lo  [n][k]
// attention operands, bf16 hi/lo
__device__ __nv_bfloat16 g_qh[BATCH * NH * SEQ * DK];  // [b,h,s,d]
__device__ __nv_bfloat16 g_ql[BATCH * NH * SEQ * DK];
__device__ __nv_bfloat16 g_kh[BATCH * NH * SEQ * DK];  // [b,h,s,d]
__device__ __nv_bfloat16 g_kl[BATCH * NH * SEQ * DK];
__device__ __nv_bfloat16 g_vh[BATCH * NH * SEQ * DK];  // [b,h,d,s]
__device__ __nv_bfloat16 g_vl[BATCH * NH * SEQ * DK];

// ===========================================================================
// small helpers
// ===========================================================================
__device__ __forceinline__ void mma16816(float* c, const uint32_t* a,
                                         const uint32_t* b)
{
    asm volatile(
        "mma.sync.aligned.m16n8k16.row.col.f32.bf16.bf16.f32 "
        "{%0,%1,%2,%3}, {%4,%5,%6,%7}, {%8,%9}, {%0,%1,%2,%3};"
        : "+f"(c[0]), "+f"(c[1]), "+f"(c[2]), "+f"(c[3])
        : "r"(a[0]), "r"(a[1]), "r"(a[2]), "r"(a[3]), "r"(b[0]), "r"(b[1]));
}

// split two fp32 into packed-bf16x2 hi word and lo word
__device__ __forceinline__ void split2(float a, float b,
                                       uint32_t& hi, uint32_t& lo) {
    __nv_bfloat16 ha = __float2bfloat16(a), hb = __float2bfloat16(b);
    __nv_bfloat16 la = __float2bfloat16(a - __bfloat162float(ha));
    __nv_bfloat16 lb = __float2bfloat16(b - __bfloat162float(hb));
    hi = ((uint32_t)__bfloat16_as_ushort(hb) << 16) | __bfloat16_as_ushort(ha);
    lo = ((uint32_t)__bfloat16_as_ushort(lb) << 16) | __bfloat16_as_ushort(la);
}

// ===========================================================================
// weight fp32 [k][n] -> bf16 hi/lo transposed [n][k]  (32x32 smem tiles)
// ===========================================================================
__global__ __launch_bounds__(256) void conv_wt(
    const float* __restrict__ W, __nv_bfloat16* __restrict__ hi,
    __nv_bfloat16* __restrict__ lo)
{
    __shared__ float t[32][33];
    int bx = blockIdx.x, by = blockIdx.y;
    int x = threadIdx.x, y = threadIdx.y;      // 32 x 8
#pragma unroll
    for (int j = 0; j < 4; j++)
        t[y + j * 8][x] = W[(size_t)(by * 32 + y + j * 8) * D_MODEL + bx * 32 + x];
    __syncthreads();
#pragma unroll
    for (int j = 0; j < 4; j++) {
        float v = t[x][y + j * 8];
        __nv_bfloat16 h = __float2bfloat16(v);
        __nv_bfloat16 l = __float2bfloat16(v - __bfloat162float(h));
        size_t o = (size_t)(bx * 32 + y + j * 8) * D_MODEL + by * 32 + x;
        hi[o] = h;
        lo[o] = l;
    }
}

// ===========================================================================
// HMMA bf16x3 GEMM, fp32 A with inline hi/lo split.
// C[4096,1024] = A_fp32[4096,1024] @ Wt[n][k]^T + bias.
// Block 128m x 256n, 512 threads / 16 warps (2m x 8n), warp tile 64x32:
//   48 LDS / 48 MMA per k16 (ratio 1.0), ~115 live regs (no spill at the
//   128-reg cap), 4 warps/SMSP, grid = 128 blocks = 1 wave.
// K-slab 32, double-buffered smem, 3 MMA products: Ah*Bh + Ah*Bl + Al*Bh.
// mode 0: write bf16 hi/lo [b,h,s,d] (Q, K)
// mode 1: write bf16 hi/lo [b,h,d,s] (V)
// mode 2: write fp32 row-major [m,n] (final out)
// ===========================================================================
#define GEMM_AH_OFF 0
#define GEMM_AL_OFF 2560
#define GEMM_BH_OFF 5120
#define GEMM_BL_OFF 10240
#define GEMM_BUF_U32 15360
#define GEMM_SMEM_BYTES (2 * GEMM_BUF_U32 * 4)     // 122880 B

__global__ __launch_bounds__(512, 1) void gemm_hmma(
    const float* __restrict__ A,
    const __nv_bfloat16* __restrict__ Bh, const __nv_bfloat16* __restrict__ Bl,
    const float* __restrict__ bias, float* __restrict__ C,
    __nv_bfloat16* __restrict__ Ch, __nv_bfloat16* __restrict__ Cl, int mode)
{
    extern __shared__ uint32_t sm32[];
    int tid = threadIdx.x;
    int wid = tid >> 5, lane = tid & 31;
    int bm = blockIdx.y * 128;
    int bn = blockIdx.x * 256;
    int wm = (wid & 1) * 64;          // 2 m-halves
    int wn = (wid >> 1) * 32;         // 8 n-groups
    int g = lane >> 2, cc = lane & 3;

    const float* Asrc = A + (size_t)bm * D_MODEL;
    const __nv_bfloat16* Bhsrc = Bh + (size_t)bn * D_MODEL;
    const __nv_bfloat16* Blsrc = Bl + (size_t)bn * D_MODEL;

    float acc[4][4][4];
#pragma unroll
    for (int i = 0; i < 4; i++)
#pragma unroll
        for (int j = 0; j < 4; j++)
#pragma unroll
            for (int u = 0; u < 4; u++) acc[i][j][u] = 0.f;

    auto load_slab = [&](int buf, int k0) {
        uint32_t* Ah_t = sm32 + buf * GEMM_BUF_U32 + GEMM_AH_OFF;
        uint32_t* Al_t = sm32 + buf * GEMM_BUF_U32 + GEMM_AL_OFF;
        uint32_t* Bh_t = sm32 + buf * GEMM_BUF_U32 + GEMM_BH_OFF;
        uint32_t* Bl_t = sm32 + buf * GEMM_BUF_U32 + GEMM_BL_OFF;
        // A: fp32 128 rows x 8 float4 segs, split inline -> hi/lo tiles
#pragma unroll
        for (int i = 0; i < 2; i++) {
            int flat = tid + i * 512;            // 0..1023
            int row = flat >> 3, seg = flat & 7;
            float4 v = *(const float4*)(Asrc + (size_t)row * D_MODEL + k0 + seg * 4);
            uint32_t h0, l0, h1, l1;
            split2(v.x, v.y, h0, l0);
            split2(v.z, v.w, h1, l1);
            *(uint2*)(Ah_t + row * 20 + seg * 2) = make_uint2(h0, h1);
            *(uint2*)(Al_t + row * 20 + seg * 2) = make_uint2(l0, l1);
        }
        // B: 256 rows x 4 uint4 segs per tile (bf16 hi and lo)
#pragma unroll
        for (int i = 0; i < 2; i++) {
            int flat = tid + i * 512;            // 0..1023
            int row = flat >> 2, seg = flat & 3;
            uint4 v = *(const uint4*)(Bhsrc + (size_t)row * D_MODEL + k0 + seg * 8);
            *(uint4*)(Bh_t + row * 20 + seg * 4) = v;
            uint4 w = *(const uint4*)(Blsrc + (size_t)row * D_MODEL + k0 + seg * 8);
            *(uint4*)(Bl_t + row * 20 + seg * 4) = w;
        }
    };

    load_slab(0, 0);
    __syncthreads();

    for (int s = 0; s < 32; s++) {
        int buf = s & 1;
        if (s + 1 < 32) load_slab(buf ^ 1, (s + 1) * 32);

        const uint32_t* As_h = sm32 + buf * GEMM_BUF_U32 + GEMM_AH_OFF;
        const uint32_t* As_l = sm32 + buf * GEMM_BUF_U32 + GEMM_AL_OFF;
        const uint32_t* Bs_h = sm32 + buf * GEMM_BUF_U32 + GEMM_BH_OFF;
        const uint32_t* Bs_l = sm32 + buf * GEMM_BUF_U32 + GEMM_BL_OFF;

#pragma unroll
        for (int ks = 0; ks < 2; ks++) {
            uint32_t bhf[4][2], blf[4][2];
#pragma unroll
            for (int j = 0; j < 4; j++) {
                int idx = (wn + j * 8 + g) * 20 + cc + ks * 8;
                bhf[j][0] = Bs_h[idx]; bhf[j][1] = Bs_h[idx + 4];
                blf[j][0] = Bs_l[idx]; blf[j][1] = Bs_l[idx + 4];
            }
#pragma unroll
            for (int i = 0; i < 4; i++) {
                int idx0 = (wm + i * 16 + g) * 20 + cc + ks * 8;
                int idx1 = idx0 + 8 * 20;
                uint32_t ahf[4] = { As_h[idx0], As_h[idx1],
                                    As_h[idx0 + 4], As_h[idx1 + 4] };
                uint32_t alf[4] = { As_l[idx0], As_l[idx1],
                                    As_l[idx0 + 4], As_l[idx1 + 4] };
#pragma unroll
                for (int j = 0; j < 4; j++) {
                    mma16816(acc[i][j], ahf, bhf[j]);
                    mma16816(acc[i][j], ahf, blf[j]);
                    mma16816(acc[i][j], alf, bhf[j]);
                }
            }
        }
        __syncthreads();
    }

#pragma unroll
    for (int i = 0; i < 4; i++) {
        int m0 = bm + wm + i * 16 + g;
#pragma unroll
        for (int j = 0; j < 4; j++) {
            int n = bn + wn + j * 8 + cc * 2;
            float b0 = bias[n], b1 = bias[n + 1];
            float v00 = acc[i][j][0] + b0, v01 = acc[i][j][1] + b1;
            float v10 = acc[i][j][2] + b0, v11 = acc[i][j][3] + b1;
            int b_ = m0 >> 11, s0 = m0 & 2047, s1 = (m0 + 8) & 2047;
            int h = n >> 6, d = n & 63;
            if (mode == 2) {
                *(float2*)&C[(size_t)m0 * D_MODEL + n]       = make_float2(v00, v01);
                *(float2*)&C[(size_t)(m0 + 8) * D_MODEL + n] = make_float2(v10, v11);
            } else if (mode == 0) {
                size_t base0 = (((size_t)(b_ * NH + h)) * SEQ + s0) * DK + d;
                size_t base1 = (((size_t)(b_ * NH + h)) * SEQ + s1) * DK + d;
                uint32_t hi0, lo0, hi1, lo1;
                split2(v00, v01, hi0, lo0);
                split2(v10, v11, hi1, lo1);
                *(uint32_t*)&Ch[base0] = hi0;  *(uint32_t*)&Cl[base0] = lo0;
                *(uint32_t*)&Ch[base1] = hi1;  *(uint32_t*)&Cl[base1] = lo1;
            } else {  // mode 1: [b,h,d,s]
                __nv_bfloat16* bch = Ch + ((size_t)(b_ * NH + h)) * DK * SEQ;
                __nv_bfloat16* bcl = Cl + ((size_t)(b_ * NH + h)) * DK * SEQ;
                float vv[4] = { v00, v01, v10, v11 };
                int ds[4]   = { d, d + 1, d, d + 1 };
                int ss[4]   = { s0, s0, s1, s1 };
#pragma unroll
                for (int u = 0; u < 4; u++) {
                    __nv_bfloat16 hh = __float2bfloat16(vv[u]);
                    __nv_bfloat16 ll = __float2bfloat16(vv[u] - __bfloat162float(hh));
                    size_t o = (size_t)ds[u] * SEQ + ss[u];
                    bch[o] = hh;
                    bcl[o] = ll;
                }
            }
        }
    }
}

// ===========================================================================
// Streaming flash-style attention (unchanged — R12/R13/R14-proven).
// 64 q-rows/block, 512 threads; scores->exp->(gmem e)+(PV) per 256-wide tile;
// shift-free softmax; attn rescaled in-block at the end.
// ===========================================================================
#define QT 64
#define EB_STRIDE 264
#define EB_SZ     (QT * EB_STRIDE)          // 16896 u32
#define KH_OFF    EB_SZ
#define KL_OFF    (KH_OFF + 8192)
#define VH_OFF    (KL_OFF + 8192)
#define VL_OFF    (VH_OFF + 8192)
#define FLASH_SMEM_U32  (VL_OFF + 8192)     // 49664 u32
#define FLASH_SMEM_BYTES (FLASH_SMEM_U32 * 4)  // 198656 B

__global__ __launch_bounds__(512, 1) void attn_flash(
    const __nv_bfloat16* __restrict__ qh, const __nv_bfloat16* __restrict__ ql,
    const __nv_bfloat16* __restrict__ kh, const __nv_bfloat16* __restrict__ kl,
    const __nv_bfloat16* __restrict__ vh, const __nv_bfloat16* __restrict__ vl,
    float* __restrict__ attn_out, float* __restrict__ ctx)
{
    extern __shared__ uint32_t sm[];
    float*    EBf = (float*)sm;
    uint32_t* KH  = sm + KH_OFF;
    uint32_t* KL  = sm + KL_OFF;
    uint32_t* VH  = sm + VH_OFF;
    uint32_t* VL  = sm + VL_OFF;

    int tid = threadIdx.x;
    int wid = tid >> 5, lane = tid & 31;
    int g = lane >> 2, cc = lane & 3;
    int qw = wid & 3, kw = wid >> 2;
    int bh = blockIdx.y;
    int b = bh >> 4, h = bh & 15;
    int q0 = blockIdx.x * QT;
    int r0 = qw * 16 + g, r1 = r0 + 8;

    const __nv_bfloat16* Qh = qh + (size_t)bh * SEQ * DK;
    const __nv_bfloat16* Ql = ql + (size_t)bh * SEQ * DK;
    const uint32_t* Kh32 = (const uint32_t*)(kh + (size_t)bh * SEQ * DK);
    const uint32_t* Kl32 = (const uint32_t*)(kl + (size_t)bh * SEQ * DK);
    const uint32_t* Vh32 = (const uint32_t*)(vh + (size_t)bh * DK * SEQ);
    const uint32_t* Vl32 = (const uint32_t*)(vl + (size_t)bh * DK * SEQ);

    uint32_t qfh[4][4], qfl[4][4];
    {
        const __nv_bfloat16* r0h = Qh + (size_t)(q0 + r0) * DK;
        const __nv_bfloat16* r1h = Qh + (size_t)(q0 + r1) * DK;
        const __nv_bfloat16* r0l = Ql + (size_t)(q0 + r0) * DK;
        const __nv_bfloat16* r1l = Ql + (size_t)(q0 + r1) * DK;
#pragma unroll
        for (int kst = 0; kst < 4; kst++) {
            int c0 = kst * 16 + cc * 2;
            qfh[kst][0] = *(const uint32_t*)(r0h + c0);
            qfh[kst][1] = *(const uint32_t*)(r1h + c0);
            qfh[kst][2] = *(const uint32_t*)(r0h + c0 + 8);
            qfh[kst][3] = *(const uint32_t*)(r1h + c0 + 8);
            qfl[kst][0] = *(const uint32_t*)(r0l + c0);
            qfl[kst][1] = *(const uint32_t*)(r1l + c0);
            qfl[kst][2] = *(const uint32_t*)(r0l + c0 + 8);
            qfl[kst][3] = *(const uint32_t*)(r1l + c0 + 8);
        }
    }

    float srow0 = 0.f, srow1 = 0.f;
    float cacc[2][4];
#pragma unroll
    for (int j = 0; j < 2; j++)
#pragma unroll
        for (int u = 0; u < 4; u++) cacc[j][u] = 0.f;

    for (int kt = 0; kt < 8; kt++) {
        __syncthreads();
#pragma unroll
        for (int i = 0; i < 4; i++) {
            int flat = tid + i * 512;
            {
                int row = flat >> 3, c4 = flat & 7;
                int dst = row * 32 + ((c4 * 4) ^ ((row & 7) << 2));
                *(uint4*)&KH[dst] = *(const uint4*)&Kh32[(size_t)(kt * 256 + row) * 32 + c4 * 4];
                *(uint4*)&KL[dst] = *(const uint4*)&Kl32[(size_t)(kt * 256 + row) * 32 + c4 * 4];
            }
            {
                int row = flat >> 5, c4 = flat & 31;
                int dst = row * 128 + ((c4 * 4) ^ ((row & 7) << 2));
                *(uint4*)&VH[dst] = *(const uint4*)&Vh32[(size_t)row * 1024 + kt * 128 + c4 * 4];
                *(uint4*)&VL[dst] = *(const uint4*)&Vl32[(size_t)row * 1024 + kt * 128 + c4 * 4];
            }
        }
        __syncthreads();

#pragma unroll
        for (int j = 0; j < 8; j++) {
            float sacc[4] = {0.f, 0.f, 0.f, 0.f};
#pragma unroll
            for (int kst = 0; kst < 4; kst++) {
                int base = (kw * 64 + j * 8 + g) * 32;
                int c0 = (cc + kst * 8) ^ (g << 2);
                int c1 = (cc + 4 + kst * 8) ^ (g << 2);
                uint32_t bhf[2] = { KH[base + c0], KH[base + c1] };
                uint32_t blf[2] = { KL[base + c0], KL[base + c1] };
                mma16816(sacc, qfh[kst], bhf);
                mma16816(sacc, qfh[kst], blf);
                mma16816(sacc, qfl[kst], bhf);
            }
            float e0 = __expf(sacc[0] * 0.125f);
            float e1 = __expf(sacc[1] * 0.125f);
            float e2 = __expf(sacc[2] * 0.125f);
            float e3 = __expf(sacc[3] * 0.125f);
            srow0 += e0 + e1;
            srow1 += e2 + e3;
            int col = kw * 64 + j * 8 + cc * 2;
            *(float2*)&EBf[r0 * EB_STRIDE + col] = make_float2(e0, e1);
            *(float2*)&EBf[r1 * EB_STRIDE + col] = make_float2(e2, e3);
        }
        __syncthreads();

#pragma unroll
        for (int i = 0; i < 8; i++) {
            int flat = tid + i * 512;
            int row = flat >> 6, c = (flat & 63) * 4;
            float4 v = *(const float4*)&EBf[row * EB_STRIDE + c];
            *(float4*)&attn_out[((size_t)bh * SEQ + q0 + row) * SEQ + kt * 256 + c] = v;
        }

#pragma unroll 2
        for (int kst = 0; kst < 16; kst++) {
            int k0 = kst * 16;
            uint32_t ahf[4], alf[4];
            float2 p;
            p = *(const float2*)&EBf[r0 * EB_STRIDE + k0 + cc * 2];
            split2(p.x, p.y, ahf[0], alf[0]);
            p = *(const float2*)&EBf[r1 * EB_STRIDE + k0 + cc * 2];
            split2(p.x, p.y, ahf[1], alf[1]);
            p = *(const float2*)&EBf[r0 * EB_STRIDE + k0 + 8 + cc * 2];
            split2(p.x, p.y, ahf[2], alf[2]);
            p = *(const float2*)&EBf[r1 * EB_STRIDE + k0 + 8 + cc * 2];
            split2(p.x, p.y, ahf[3], alf[3]);
#pragma unroll
            for (int j = 0; j < 2; j++) {
                int base = (kw * 16 + j * 8 + g) * 128;
                int c0 = (cc + kst * 8) ^ (g << 2);
                int c1 = (cc + 4 + kst * 8) ^ (g << 2);
                uint32_t bhf[2] = { VH[base + c0], VH[base + c1] };
                uint32_t blf[2] = { VL[base + c0], VL[base + c1] };
                mma16816(cacc[j], ahf, bhf);
                mma16816(cacc[j], ahf, blf);
                mma16816(cacc[j], alf, bhf);
            }
        }
    }
    __syncthreads();

    srow0 += __shfl_xor_sync(0xffffffffu, srow0, 1);
    srow0 += __shfl_xor_sync(0xffffffffu, srow0, 2);
    srow1 += __shfl_xor_sync(0xffffffffu, srow1, 1);
    srow1 += __shfl_xor_sync(0xffffffffu, srow1, 2);
    if (cc == 0) {
        EBf[r0 * 4 + kw] = srow0;
        EBf[r1 * 4 + kw] = srow1;
    }
    __syncthreads();
    if (tid < 64) {
        float s = EBf[tid * 4] + EBf[tid * 4 + 1] + EBf[tid * 4 + 2] + EBf[tid * 4 + 3];
        EBf[256 + tid] = 1.0f / s;
    }
    __syncthreads();

    {
        float inv0 = EBf[256 + r0], inv1 = EBf[256 + r1];
#pragma unroll
        for (int j = 0; j < 2; j++) {
            int col = h * DK + kw * 16 + j * 8 + cc * 2;
            *(float2*)&ctx[((size_t)(b * SEQ) + q0 + r0) * D_MODEL + col] =
                make_float2(cacc[j][0] * inv0, cacc[j][1] * inv0);
            *(float2*)&ctx[((size_t)(b * SEQ) + q0 + r1) * D_MODEL + col] =
                make_float2(cacc[j][2] * inv1, cacc[j][3] * inv1);
        }
    }

    {
        int row = tid >> 3, t8 = tid & 7;
        float inv = EBf[256 + row];
        float* arow = attn_out + ((size_t)bh * SEQ + q0 + row) * SEQ;
#pragma unroll 4
        for (int i = 0; i < 64; i++) {
            int c = (t8 + i * 8) * 4;
            float4 v = *(float4*)&arow[c];
            v.x *= inv; v.y *= inv; v.z *= inv; v.w *= inv;
            *(float4*)&arow[c] = v;
        }
    }
}

// ---------------------------------------------------------------------------
extern "C" void kernel_launch(void* const* d_in, const int* in_sizes, int n_in,
                              void* d_out, int out_size)
{
    const float* query = (const float*)d_in[0];
    const float* key   = (const float*)d_in[1];
    const float* value = (const float*)d_in[2];
    const float* Wq = (const float*)d_in[3];
    const float* bq = (const float*)d_in[4];
    const float* Wk = (const float*)d_in[5];
    const float* bk = (const float*)d_in[6];
    const float* Wv = (const float*)d_in[7];
    const float* bv = (const float*)d_in[8];
    const float* Wo = (const float*)d_in[9];
    const float* bo = (const float*)d_in[10];

    float* out  = (float*)d_out;
    float* attn = out + OUT_ELEMS;

    float* gctx;
    __nv_bfloat16 *bh_, *bl_, *qh, *ql, *kh, *kl, *vh, *vl;
    cudaGetSymbolAddress((void**)&gctx, g_ctx);
    cudaGetSymbolAddress((void**)&bh_,  g_bh);
    cudaGetSymbolAddress((void**)&bl_,  g_bl);
    cudaGetSymbolAddress((void**)&qh,   g_qh);
    cudaGetSymbolAddress((void**)&ql,   g_ql);
    cudaGetSymbolAddress((void**)&kh,   g_kh);
    cudaGetSymbolAddress((void**)&kl,   g_kl);
    cudaGetSymbolAddress((void**)&vh,   g_vh);
    cudaGetSymbolAddress((void**)&vl,   g_vl);

    cudaFuncSetAttribute(gemm_hmma,
                         cudaFuncAttributeMaxDynamicSharedMemorySize,
                         GEMM_SMEM_BYTES);
    cudaFuncSetAttribute(attn_flash,
                         cudaFuncAttributeMaxDynamicSharedMemorySize,
                         FLASH_SMEM_BYTES);

    dim3 gg(D_MODEL / 256, M_ROWS / 128);     // (4, 32) = 128 blocks = 1 wave
    dim3 wtg(32, 32);
    dim3 wtb(32, 8);

    // Q projection -> bf16 hi/lo [b,h,s,d]   (fp32 A, inline split)
    conv_wt<<<wtg, wtb>>>(Wq, bh_, bl_);
    gemm_hmma<<<gg, 512, GEMM_SMEM_BYTES>>>(query, bh_, bl_, bq, nullptr, qh, ql, 0);
    // K projection -> bf16 hi/lo [b,h,s,d]
    conv_wt<<<wtg, wtb>>>(Wk, bh_, bl_);
    gemm_hmma<<<gg, 512, GEMM_SMEM_BYTES>>>(key, bh_, bl_, bk, nullptr, kh, kl, 0);
    // V projection -> bf16 hi/lo [b,h,d,s]
    conv_wt<<<wtg, wtb>>>(Wv, bh_, bl_);
    gemm_hmma<<<gg, 512, GEMM_SMEM_BYTES>>>(value, bh_, bl_, bv, nullptr, vh, vl, 1);

    // streaming attention (scores+softmax+attn-write+PV fused)
    attn_flash<<<dim3(SEQ / QT, BATCH * NH), 512, FLASH_SMEM_BYTES>>>(
        qh, ql, kh, kl, vh, vl, attn, gctx);

    // output projection (fp32 A = ctx, fp32 out)
    conv_wt<<<wtg, wtb>>>(Wo, bh_, bl_);
    gemm_hmma<<<gg, 512, GEMM_SMEM_BYTES>>>(gctx, bh_, bl_, bo, out, nullptr, nullptr, 2);
}